// round 1
// baseline (speedup 1.0000x reference)
#include <cuda_runtime.h>
#include <math.h>

#define B_ 4
#define L_ 4096
#define DM_ 1024
#define H_ 16
#define DH_ 64
#define K_ 8
#define C_ 512
#define BL_ (B_*L_)      /* 16384 */
#define HD_ (H_*DH_)     /* 1024  */

/* ------------ device scratch (static allocation, no cudaMalloc) ---------- */
__device__ float g_q[BL_*HD_];
__device__ float g_k[BL_*HD_];
__device__ float g_v[BL_*HD_];
__device__ float g_o[BL_*HD_];
__device__ int   g_bid_q[B_*H_*L_];
__device__ int   g_bid_k[B_*H_*L_];
__device__ int   g_srt_q[B_*H_*L_];
__device__ int   g_srt_k[B_*H_*L_];
__device__ float g_mix_q[H_*DH_*K_];
__device__ float g_mix_k[H_*DH_*K_];
__device__ float g_psum_q[B_*H_*K_];
__device__ float g_fsum_q[B_*H_*K_];
__device__ float g_psum_k[B_*H_*K_];
__device__ float g_fsum_k[B_*H_*K_];

/* -------------------------- prep: mix weights + zero loss accum ---------- */
__global__ void prep_kernel(const float* __restrict__ wsh,
                            const float* __restrict__ wqs,
                            const float* __restrict__ wks) {
    int i = blockIdx.x * blockDim.x + threadIdx.x;
    if (i < H_*DH_*K_) {
        float s = wsh[i];
        g_mix_q[i] = 0.9f * s + 0.1f * wqs[i];
        g_mix_k[i] = 0.9f * s + 0.1f * wks[i];
    }
    if (i < B_*H_*K_) {
        g_psum_q[i] = 0.f; g_fsum_q[i] = 0.f;
        g_psum_k[i] = 0.f; g_fsum_k[i] = 0.f;
    }
}

/* -------------------------- GEMM: C[M,N] = A[M,K]*B[K,N] + bias[N] ------- */
/* 128x128 tile, BK=16, 256 threads, 8x8 per thread. M,N,K all multiples.   */
#define BM 128
#define BN 128
#define BK 16
__global__ __launch_bounds__(256) void gemm_bias_kernel(
    const float* __restrict__ A, const float* __restrict__ Bm,
    const float* __restrict__ bias, float* __restrict__ C,
    int M, int N, int Kd) {
    __shared__ float As[BK][BM + 4];
    __shared__ float Bs[BK][BN];
    int tid = threadIdx.x;
    int brow = blockIdx.y * BM;
    int bcol = blockIdx.x * BN;
    int tx = tid & 15;          /* n sub-tile */
    int ty = tid >> 4;          /* m sub-tile */
    float acc[8][8];
#pragma unroll
    for (int i = 0; i < 8; i++)
#pragma unroll
        for (int j = 0; j < 8; j++) acc[i][j] = 0.f;

    for (int k0 = 0; k0 < Kd; k0 += BK) {
#pragma unroll
        for (int i = 0; i < 2; i++) {
            int lin = tid + i * 256;          /* 0..511 */
            int r = lin >> 2;                 /* 0..127 */
            int kc = (lin & 3) * 4;           /* 0,4,8,12 */
            float4 av = *(const float4*)(A + (size_t)(brow + r) * Kd + k0 + kc);
            As[kc + 0][r] = av.x; As[kc + 1][r] = av.y;
            As[kc + 2][r] = av.z; As[kc + 3][r] = av.w;
        }
#pragma unroll
        for (int i = 0; i < 2; i++) {
            int lin = tid + i * 256;
            int r = lin >> 5;                 /* 0..15 */
            int c = (lin & 31) * 4;           /* 0..124 */
            *(float4*)&Bs[r][c] = *(const float4*)(Bm + (size_t)(k0 + r) * N + bcol + c);
        }
        __syncthreads();
#pragma unroll
        for (int kk = 0; kk < BK; kk++) {
            float4 a0 = *(const float4*)&As[kk][ty * 8];
            float4 a1 = *(const float4*)&As[kk][ty * 8 + 4];
            float4 b0 = *(const float4*)&Bs[kk][tx * 8];
            float4 b1 = *(const float4*)&Bs[kk][tx * 8 + 4];
            float a[8] = {a0.x,a0.y,a0.z,a0.w,a1.x,a1.y,a1.z,a1.w};
            float bb[8] = {b0.x,b0.y,b0.z,b0.w,b1.x,b1.y,b1.z,b1.w};
#pragma unroll
            for (int i = 0; i < 8; i++)
#pragma unroll
                for (int j = 0; j < 8; j++) acc[i][j] += a[i] * bb[j];
        }
        __syncthreads();
    }
#pragma unroll
    for (int i = 0; i < 8; i++) {
        int r = brow + ty * 8 + i;
#pragma unroll
        for (int j = 0; j < 8; j += 4) {
            int c = bcol + tx * 8 + j;
            float4 ov = make_float4(acc[i][j]   + bias[c],
                                    acc[i][j+1] + bias[c+1],
                                    acc[i][j+2] + bias[c+2],
                                    acc[i][j+3] + bias[c+3]);
            *(float4*)(C + (size_t)r * N + c) = ov;
        }
    }
}

/* ------------- scores + argmax bucket id + loss accumulators ------------- */
__global__ __launch_bounds__(256) void score_kernel(
    const float* __restrict__ x,     /* [B,L,H,DH] */
    const float* __restrict__ mix,   /* [H,DH,K]   */
    int* __restrict__ bid,           /* [B,H,L]    */
    float* __restrict__ p_sum,       /* [B,H,K]    */
    float* __restrict__ f_sum) {
    __shared__ float smix[H_*DH_*K_];          /* 32 KB */
    __shared__ float red_p[16][K_];
    __shared__ float red_f[16][K_];
    int tid = threadIdx.x;
    for (int i = tid; i < H_*DH_*K_; i += 256) smix[i] = mix[i];
    if (tid < 128) { ((float*)red_p)[tid] = 0.f; ((float*)red_f)[tid] = 0.f; }
    __syncthreads();

    /* remap so h varies slowly inside the warp (fewer smem conflicts) */
    int h  = tid >> 4;
    int li = tid & 15;
    int gid = blockIdx.x * 256 + li * H_ + h;   /* (b*L+l)*H + h */
    int l = (gid / H_) & (L_ - 1);
    int b = gid / (H_ * L_);

    const float4* row4 = (const float4*)(x + (size_t)gid * DH_);
    const float* mh = smix + h * DH_ * K_;
    float s[K_];
#pragma unroll
    for (int k = 0; k < K_; k++) s[k] = 0.f;
#pragma unroll
    for (int d4 = 0; d4 < 16; d4++) {
        float4 xv = row4[d4];
        const float* m0 = mh + (d4*4) * K_;
#pragma unroll
        for (int k = 0; k < K_; k++) {
            s[k] += xv.x * m0[k] + xv.y * m0[K_ + k]
                  + xv.z * m0[2*K_ + k] + xv.w * m0[3*K_ + k];
        }
    }
    int am = 0; float mx = s[0];
#pragma unroll
    for (int k = 1; k < K_; k++) if (s[k] > mx) { mx = s[k]; am = k; }
    bid[(b * H_ + h) * L_ + l] = am;

    float esum = 0.f; float e[K_];
#pragma unroll
    for (int k = 0; k < K_; k++) { e[k] = __expf(s[k] - mx); esum += e[k]; }
    float inv = 1.f / esum;
#pragma unroll
    for (int k = 0; k < K_; k++) atomicAdd(&red_p[h][k], e[k] * inv);
    atomicAdd(&red_f[h][am], 1.f);
    __syncthreads();
    if (tid < 128) {
        int hh = tid / K_, kk = tid % K_;
        atomicAdd(&p_sum[(b * H_ + hh) * K_ + kk], red_p[hh][kk]);
        atomicAdd(&f_sum[(b * H_ + hh) * K_ + kk], red_f[hh][kk]);
    }
}

/* ------------- stable counting sort by bucket id, per (b,h) -------------- */
__global__ __launch_bounds__(512) void sort_kernel(const int* __restrict__ bid,
                                                   int* __restrict__ srt) {
    __shared__ int cnt[K_][513];
    __shared__ int bstart[K_];
    int bh = blockIdx.x;
    const int* bb = bid + (size_t)bh * L_;
    int t = threadIdx.x;
    int myb[8];
    int local[K_];
#pragma unroll
    for (int k = 0; k < K_; k++) local[k] = 0;
#pragma unroll
    for (int j = 0; j < 8; j++) { myb[j] = bb[t * 8 + j]; local[myb[j]]++; }
#pragma unroll
    for (int k = 0; k < K_; k++) cnt[k][t + 1] = local[k];
    if (t < K_) cnt[t][0] = 0;
    __syncthreads();
    if (t < K_) {
        int run = 0;
        for (int i = 1; i <= 512; i++) { run += cnt[t][i]; cnt[t][i] = run; }
    }
    __syncthreads();
    if (t == 0) {
        int a = 0;
        for (int k = 0; k < K_; k++) { bstart[k] = a; a += cnt[k][512]; }
    }
    __syncthreads();
    int off[K_];
#pragma unroll
    for (int k = 0; k < K_; k++) off[k] = bstart[k] + cnt[k][t];
    int* so = srt + (size_t)bh * L_;
#pragma unroll
    for (int j = 0; j < 8; j++) {
        int bkt = myb[j];
        so[off[bkt]++] = t * 8 + j;
    }
}

/* ----------------------- chunked flash attention ------------------------- */
/* block = 128 q rows (1/thread), loops 16 K/V tiles of 32 rows.             */
__global__ __launch_bounds__(128) void attn_kernel() {
    __shared__ float Ks[32][DH_];
    __shared__ float Vs[32][DH_];
    int tid = threadIdx.x;
    int idx = blockIdx.x;
    int qt    = idx & 3;
    int chunk = (idx >> 2) & (K_ - 1);
    int h     = (idx >> 5) & (H_ - 1);
    int b     = idx >> 9;
    int base  = (b * H_ + h) * L_;

    int qi = g_srt_q[base + chunk * C_ + qt * 128 + tid];
    const float4* q4 = (const float4*)(g_q + ((size_t)(b * L_ + qi) * H_ + h) * DH_);
    float qreg[DH_];
#pragma unroll
    for (int d4 = 0; d4 < 16; d4++) {
        float4 tq = q4[d4];
        qreg[d4*4+0] = tq.x * 0.125f; qreg[d4*4+1] = tq.y * 0.125f;
        qreg[d4*4+2] = tq.z * 0.125f; qreg[d4*4+3] = tq.w * 0.125f;
    }
    float acc[DH_];
#pragma unroll
    for (int d = 0; d < DH_; d++) acc[d] = 0.f;
    float m = -1e30f, lsum = 0.f;

    for (int t = 0; t < 16; t++) {
        __syncthreads();
#pragma unroll
        for (int i = 0; i < 4; i++) {
            int lin = tid + i * 128;          /* 0..511 */
            int r = lin >> 4, c4 = lin & 15;
            int ki = g_srt_k[base + chunk * C_ + t * 32 + r];
            size_t rowo = ((size_t)(b * L_ + ki) * H_ + h) * DH_;
            ((float4*)Ks[r])[c4] = ((const float4*)(g_k + rowo))[c4];
            ((float4*)Vs[r])[c4] = ((const float4*)(g_v + rowo))[c4];
        }
        __syncthreads();

        float sreg[32];
        float tmax = -1e30f;
#pragma unroll
        for (int c = 0; c < 32; c++) {
            const float4* kr = (const float4*)Ks[c];
            float s = 0.f;
#pragma unroll
            for (int d4 = 0; d4 < 16; d4++) {
                float4 kv = kr[d4];
                s += qreg[d4*4+0]*kv.x + qreg[d4*4+1]*kv.y
                   + qreg[d4*4+2]*kv.z + qreg[d4*4+3]*kv.w;
            }
            sreg[c] = s;
            tmax = fmaxf(tmax, s);
        }
        float mnew = fmaxf(m, tmax);
        float corr = __expf(m - mnew);
        lsum *= corr;
#pragma unroll
        for (int d = 0; d < DH_; d++) acc[d] *= corr;
#pragma unroll
        for (int c = 0; c < 32; c++) {
            float p = __expf(sreg[c] - mnew);
            lsum += p;
            const float4* vr = (const float4*)Vs[c];
#pragma unroll
            for (int d4 = 0; d4 < 16; d4++) {
                float4 vv = vr[d4];
                acc[d4*4+0] += p * vv.x; acc[d4*4+1] += p * vv.y;
                acc[d4*4+2] += p * vv.z; acc[d4*4+3] += p * vv.w;
            }
        }
        m = mnew;
    }
    float invl = 1.f / lsum;
    float* orow = g_o + ((size_t)(b * L_ + qi) * H_ + h) * DH_;  /* scatter = unsort */
#pragma unroll
    for (int d4 = 0; d4 < 16; d4++) {
        float4 ov = make_float4(acc[d4*4]*invl, acc[d4*4+1]*invl,
                                acc[d4*4+2]*invl, acc[d4*4+3]*invl);
        ((float4*)orow)[d4] = ov;
    }
}

/* ----------------------------- loss finalize ----------------------------- */
__global__ void loss_kernel(float* __restrict__ out, int out_size) {
    if (out_size <= BL_ * DM_) return;
    float lq = 0.f, lk = 0.f;
    const float invL = 1.f / (float)L_;
    for (int i = 0; i < B_ * H_; i++) {
        float aq = 0.f, ak = 0.f;
        for (int k = 0; k < K_; k++) {
            aq += (g_fsum_q[i*K_+k] * invL) * (g_psum_q[i*K_+k] * invL);
            ak += (g_fsum_k[i*K_+k] * invL) * (g_psum_k[i*K_+k] * invL);
        }
        lq += aq; lk += ak;
    }
    lq = (float)K_ * lq / (float)(B_ * H_);
    lk = (float)K_ * lk / (float)(B_ * H_);
    out[BL_ * DM_] = 0.5f * (lq + lk);
}

/* ------------------------------- launch ---------------------------------- */
extern "C" void kernel_launch(void* const* d_in, const int* in_sizes, int n_in,
                              void* d_out, int out_size) {
    const float* x   = (const float*)d_in[0];
    const float* wq  = (const float*)d_in[1];
    const float* bq  = (const float*)d_in[2];
    const float* wk  = (const float*)d_in[3];
    const float* bk  = (const float*)d_in[4];
    const float* wv  = (const float*)d_in[5];
    const float* bv  = (const float*)d_in[6];
    const float* wsh = (const float*)d_in[7];
    const float* wqs = (const float*)d_in[8];
    const float* wks = (const float*)d_in[9];
    const float* wo  = (const float*)d_in[10];
    const float* bo  = (const float*)d_in[11];
    float* out = (float*)d_out;

    void* p;
    cudaGetSymbolAddress(&p, g_q);     float* q_ptr   = (float*)p;
    cudaGetSymbolAddress(&p, g_k);     float* k_ptr   = (float*)p;
    cudaGetSymbolAddress(&p, g_v);     float* v_ptr   = (float*)p;
    cudaGetSymbolAddress(&p, g_o);     float* o_ptr   = (float*)p;
    cudaGetSymbolAddress(&p, g_mix_q); float* mixq    = (float*)p;
    cudaGetSymbolAddress(&p, g_mix_k); float* mixk    = (float*)p;
    cudaGetSymbolAddress(&p, g_bid_q); int*   bidq    = (int*)p;
    cudaGetSymbolAddress(&p, g_bid_k); int*   bidk    = (int*)p;
    cudaGetSymbolAddress(&p, g_srt_q); int*   srtq    = (int*)p;
    cudaGetSymbolAddress(&p, g_srt_k); int*   srtk    = (int*)p;
    cudaGetSymbolAddress(&p, g_psum_q); float* psq = (float*)p;
    cudaGetSymbolAddress(&p, g_fsum_q); float* fsq = (float*)p;
    cudaGetSymbolAddress(&p, g_psum_k); float* psk = (float*)p;
    cudaGetSymbolAddress(&p, g_fsum_k); float* fsk = (float*)p;

    prep_kernel<<<32, 256>>>(wsh, wqs, wks);

    dim3 ggrid(HD_ / BN, BL_ / BM);
    gemm_bias_kernel<<<ggrid, 256>>>(x, wq, bq, q_ptr, BL_, HD_, DM_);
    gemm_bias_kernel<<<ggrid, 256>>>(x, wk, bk, k_ptr, BL_, HD_, DM_);
    gemm_bias_kernel<<<ggrid, 256>>>(x, wv, bv, v_ptr, BL_, HD_, DM_);

    score_kernel<<<(BL_ * H_) / 256, 256>>>(q_ptr, mixq, bidq, psq, fsq);
    score_kernel<<<(BL_ * H_) / 256, 256>>>(k_ptr, mixk, bidk, psk, fsk);

    sort_kernel<<<B_ * H_, 512>>>(bidq, srtq);
    sort_kernel<<<B_ * H_, 512>>>(bidk, srtk);

    attn_kernel<<<B_ * H_ * K_ * (C_ / 128), 128>>>();

    dim3 ogrid(DM_ / BN, BL_ / BM);
    gemm_bias_kernel<<<ogrid, 256>>>(o_ptr, wo, bo, out, BL_, DM_, HD_);

    loss_kernel<<<1, 1>>>(out, out_size);
}